// round 13
// baseline (speedup 1.0000x reference)
#include <cuda_runtime.h>
#include <cuda_bf16.h>
#include <cuda_fp16.h>
#include <math.h>
#include <stdint.h>

// Problem dims
#define T1 63
#define BB 32
#define HH 512
#define VV 32000
#define MR (T1*BB)       // 2016
#define GD (4*HH)        // 2048
#define KX 1024          // xs K-dim
#define NTB 250          // logits n-blocks (128 wide)

// Scratch (device globals)
__device__ float g_gx[(size_t)MR * GD];
__device__ float g_hs[(size_t)MR * HH];
__device__ unsigned g_bar;
__device__ __half g_wh[(size_t)VV * HH];      // W_out fp16
__device__ __half g_hsh[(size_t)MR * HH];     // h states fp16
__device__ __half g_wih_h[(size_t)GD * KX];   // W_ih hi
__device__ __half g_wih_l[(size_t)GD * KX];   // W_ih lo
__device__ __half g_xs_h[(size_t)MR * KX];    // xs hi
__device__ __half g_xs_l[(size_t)MR * KX];    // xs lo
__device__ __half g_hbh[2][BB * HH];          // h double-buffer (fp16)
__device__ unsigned g_tmax[(size_t)MR * NTB]; // per-(row, nblock) max key

#define NCTA 128
#define SHP 520
#define SREDP 18
#define LSTM_SMEM_BYTES ((32+16+16)*SHP*2 + 8*32*SREDP*4 + 128*4)  // 85,504

__device__ __forceinline__ uint32_t smem_u32(const void* p) {
    uint32_t a;
    asm("{ .reg .u64 t; cvta.to.shared.u64 t, %1; cvt.u32.u64 %0, t; }"
        : "=r"(a) : "l"(p));
    return a;
}
__device__ __forceinline__ unsigned fkey(float x) {
    unsigned u = __float_as_uint(x);
    return (u & 0x80000000u) ? ~u : (u | 0x80000000u);
}
__device__ __forceinline__ float keyf(unsigned k) {
    unsigned u = (k & 0x80000000u) ? (k & 0x7FFFFFFFu) : ~k;
    return __uint_as_float(u);
}

#define LDMX4(R, addr) \
    asm volatile("ldmatrix.sync.aligned.m8n8.x4.shared.b16 {%0,%1,%2,%3}, [%4];" \
        : "=r"((R)[0]), "=r"((R)[1]), "=r"((R)[2]), "=r"((R)[3]) : "r"(addr))

#define MMA16816F(C, A, B0, B1) \
    asm volatile("mma.sync.aligned.m16n8k16.row.col.f32.f16.f16.f32 " \
        "{%0,%1,%2,%3}, {%4,%5,%6,%7}, {%8,%9}, {%0,%1,%2,%3};" \
        : "+f"((C)[0]), "+f"((C)[1]), "+f"((C)[2]), "+f"((C)[3]) \
        : "r"((A)[0]), "r"((A)[1]), "r"((A)[2]), "r"((A)[3]), "r"(B0), "r"(B1))

__device__ __forceinline__ void split16(float x, __half& h, __half& l) {
    h = __float2half_rn(x);
    l = __float2half_rn(x - __half2float(h));
}

// ---------------------------------------------------------------------------
// One fat converter kernel (R11-proven).
// ---------------------------------------------------------------------------
__global__ void convert_all(const float* __restrict__ Wout,
                            const float* __restrict__ Wih,
                            const float* __restrict__ enc,
                            const int* __restrict__ cap,
                            const float* __restrict__ emb)
{
    const int bid = blockIdx.x;
    if (bid == 0 && threadIdx.x == 0) g_bar = 0u;

    if (bid < 16000) {
        size_t i = ((size_t)bid * 256 + threadIdx.x) * 4;
        float4 v = *(const float4*)(Wout + i);
        __half2 a = __floats2half2_rn(v.x, v.y);
        __half2 b = __floats2half2_rn(v.z, v.w);
        uint2 o; o.x = *(uint32_t*)&a; o.y = *(uint32_t*)&b;
        *(uint2*)(g_wh + i) = o;
    } else if (bid < 18048) {
        size_t i = ((size_t)(bid - 16000) * 256 + threadIdx.x) * 4;
        float4 v = *(const float4*)(Wih + i);
        __half h0, l0, h1, l1, h2, l2, h3, l3;
        split16(v.x, h0, l0); split16(v.y, h1, l1);
        split16(v.z, h2, l2); split16(v.w, h3, l3);
        __half2 ha = __halves2half2(h0, h1), hb = __halves2half2(h2, h3);
        __half2 la = __halves2half2(l0, l1), lb = __halves2half2(l2, l3);
        uint2 oh, ol;
        oh.x = *(uint32_t*)&ha; oh.y = *(uint32_t*)&hb;
        ol.x = *(uint32_t*)&la; ol.y = *(uint32_t*)&lb;
        *(uint2*)(g_wih_h + i) = oh;
        *(uint2*)(g_wih_l + i) = ol;
    } else {
        int i4 = (bid - 18048) * 256 + threadIdx.x;   // float4 index
        int m = i4 >> 8;
        int c4 = i4 & 255;
        int k = c4 * 4;
        int tt = m >> 5, b = m & 31;
        const float* src = (k < 512)
            ? (enc + b * 512 + k)
            : (emb + (size_t)__ldg(cap + b * 64 + tt) * 512 + (k - 512));
        float4 v = *(const float4*)src;
        __half h0, l0, h1, l1, h2, l2, h3, l3;
        split16(v.x, h0, l0); split16(v.y, h1, l1);
        split16(v.z, h2, l2); split16(v.w, h3, l3);
        __half2 ha = __halves2half2(h0, h1), hb = __halves2half2(h2, h3);
        __half2 la = __halves2half2(l0, l1), lb = __halves2half2(l2, l3);
        uint2 oh, ol;
        oh.x = *(uint32_t*)&ha; oh.y = *(uint32_t*)&hb;
        ol.x = *(uint32_t*)&la; ol.y = *(uint32_t*)&lb;
        size_t off = (size_t)m * KX + k;
        *(uint2*)(g_xs_h + off) = oh;
        *(uint2*)(g_xs_l + off) = ol;
    }
}

// ---------------------------------------------------------------------------
// gx GEMM via fp16x2-split mma.sync (R8-proven, unchanged).
// ---------------------------------------------------------------------------
#define SAP 40
#define TILEB (128 * SAP * 2)
#define BUFB  (2 * TILEB)
#define AB_REGION (2 * BUFB)
#define GX_SMEM (2 * AB_REGION + 512)

#define GX_ISSUE(ch) do { \
    int _buf = (ch) & 1; int _k0 = (ch) * 32; \
    _Pragma("unroll") \
    for (int _it = 0; _it < 8; _it++) { \
        const int _sel = _it >> 1; \
        int _rem = tid + (_it & 1) * 256; \
        int _r = _rem >> 2, _c8 = (_rem & 3) * 8; \
        uint32_t _dst = (_sel < 2 ? sAu : sBu) + _buf * BUFB \
                      + (_sel & 1) * TILEB + (uint32_t)(_r * SAP + _c8) * 2; \
        if (_sel < 2) { \
            int _gm = m0 + _r; \
            const __half* _src = (_sel == 0 ? g_xs_h : g_xs_l) \
                + (size_t)(_gm < MR ? _gm : 0) * KX + _k0 + _c8; \
            int _sz = (_gm < MR) ? 16 : 0; \
            asm volatile("cp.async.cg.shared.global [%0], [%1], 16, %2;\n" \
                         :: "r"(_dst), "l"(_src), "r"(_sz)); \
        } else { \
            const __half* _src = (_sel == 2 ? g_wih_h : g_wih_l) \
                + (size_t)(n0 + _r) * KX + _k0 + _c8; \
            asm volatile("cp.async.cg.shared.global [%0], [%1], 16;\n" \
                         :: "r"(_dst), "l"(_src)); \
        } \
    } \
    asm volatile("cp.async.commit_group;\n"); \
} while (0)

__global__ __launch_bounds__(256) void gemm_gx_f16(
    const float* __restrict__ bih, const float* __restrict__ bhh)
{
    extern __shared__ char dyn[];
    const uint32_t sAu = smem_u32(dyn);
    const uint32_t sBu = sAu + AB_REGION;
    float* sbias = (float*)(dyn + 2 * AB_REGION);

    const int tid = threadIdx.x, lane = tid & 31, wid = tid >> 5;
    const int m0 = blockIdx.x * 128, n0 = blockIdx.y * 128;
    const int wm = (wid & 1) * 64, wn = (wid >> 1) * 32;

    if (tid < 128) sbias[tid] = bih[n0 + tid] + bhh[n0 + tid];

    const int rowA = lane & 15;
    const int kA   = (lane >> 4) << 3;
    const int rowB = (lane & 7) + ((lane >> 4) << 3);
    const int kB   = (lane & 8) ? 8 : 0;

    float c[4][4][4];
#pragma unroll
    for (int mi = 0; mi < 4; mi++)
#pragma unroll
        for (int ni = 0; ni < 4; ni++)
#pragma unroll
            for (int q = 0; q < 4; q++) c[mi][ni][q] = 0.f;

    GX_ISSUE(0);

    for (int ch = 0; ch < 32; ch++) {
        const int buf = ch & 1;
        if (ch < 31) {
            GX_ISSUE(ch + 1);
            asm volatile("cp.async.wait_group 1;\n");
        } else {
            asm volatile("cp.async.wait_group 0;\n");
        }
        __syncthreads();

#pragma unroll
        for (int kk = 0; kk < 32; kk += 16) {
            uint32_t aH[4][4], aL[4][4], bH[4][2], bL[4][2];
#pragma unroll
            for (int mi = 0; mi < 4; mi++) {
                uint32_t base = sAu + buf * BUFB +
                    (uint32_t)((wm + mi * 16 + rowA) * SAP + kk + kA) * 2;
                LDMX4(aH[mi], base);
                LDMX4(aL[mi], base + TILEB);
            }
#pragma unroll
            for (int nb = 0; nb < 2; nb++) {
                uint32_t base = sBu + buf * BUFB +
                    (uint32_t)((wn + nb * 16 + rowB) * SAP + kk + kB) * 2;
                uint32_t r4[4];
                LDMX4(r4, base);
                bH[2 * nb][0] = r4[0]; bH[2 * nb][1] = r4[1];
                bH[2 * nb + 1][0] = r4[2]; bH[2 * nb + 1][1] = r4[3];
                LDMX4(r4, base + TILEB);
                bL[2 * nb][0] = r4[0]; bL[2 * nb][1] = r4[1];
                bL[2 * nb + 1][0] = r4[2]; bL[2 * nb + 1][1] = r4[3];
            }
#pragma unroll
            for (int mi = 0; mi < 4; mi++)
#pragma unroll
                for (int ni = 0; ni < 4; ni++) {
                    MMA16816F(c[mi][ni], aH[mi], bH[ni][0], bH[ni][1]);
                    MMA16816F(c[mi][ni], aH[mi], bL[ni][0], bL[ni][1]);
                    MMA16816F(c[mi][ni], aL[mi], bH[ni][0], bH[ni][1]);
                }
        }
        __syncthreads();
    }

    const int erow = lane >> 2;
    const int ecol = (lane & 3) * 2;
#pragma unroll
    for (int mi = 0; mi < 4; mi++) {
#pragma unroll
        for (int half = 0; half < 2; half++) {
            int gm = m0 + wm + mi * 16 + erow + half * 8;
            if (gm < MR) {
                float* dst = g_gx + (size_t)gm * GD + n0 + wn;
#pragma unroll
                for (int ni = 0; ni < 4; ni++) {
                    float2 o;
                    o.x = c[mi][ni][half * 2 + 0] + sbias[wn + ni * 8 + ecol + 0];
                    o.y = c[mi][ni][half * 2 + 1] + sbias[wn + ni * 8 + ecol + 1];
                    *(float2*)(dst + ni * 8 + ecol) = o;
                }
            }
        }
    }
}

// ---------------------------------------------------------------------------
// Persistent LSTM (R11-proven, unchanged).
// ---------------------------------------------------------------------------
__device__ __forceinline__ void grid_barrier_rel(unsigned target) {
    __syncthreads();
    if (threadIdx.x == 0) {
        unsigned a;
        asm volatile("atom.release.gpu.global.add.u32 %0, [%1], 1;"
                     : "=r"(a) : "l"(&g_bar) : "memory");
        a += 1;
        if (a < target) {
            unsigned v;
            do {
                asm volatile("ld.acquire.gpu.global.u32 %0, [%1];"
                             : "=r"(v) : "l"(&g_bar) : "memory");
            } while (v < target);
        }
    }
    __syncthreads();
}

__global__ __launch_bounds__(512, 1) void lstm_persist(const float* __restrict__ Whh)
{
    extern __shared__ char dsm[];
    __half* sHh = (__half*)dsm;                 // [32][SHP]
    __half* sWh = sHh + 32 * SHP;               // [16][SHP]
    __half* sWl = sWh + 16 * SHP;               // [16][SHP]
    float*  sRed = (float*)(sWl + 16 * SHP);    // [8][32][SREDP]
    float*  sC   = sRed + 8 * 32 * SREDP;       // [128]

    const int tid = threadIdx.x, lane = tid & 31, wid = tid >> 5;
    const int j0 = blockIdx.x * 4;

    for (int i = tid; i < 16 * 128; i += 512) {   // float4 units
        int row = i >> 7, c4 = i & 127;
        int g = row >> 2, j = row & 3;
        float4 v = *(const float4*)(Whh + (size_t)(g * 512 + j0 + j) * 512 + c4 * 4);
        __half h0, l0, h1, l1, h2, l2, h3, l3;
        split16(v.x, h0, l0); split16(v.y, h1, l1);
        split16(v.z, h2, l2); split16(v.w, h3, l3);
        __half2 ha = __halves2half2(h0, h1), hb = __halves2half2(h2, h3);
        __half2 la = __halves2half2(l0, l1), lb = __halves2half2(l2, l3);
        uint2 oh, ol;
        oh.x = *(uint32_t*)&ha; oh.y = *(uint32_t*)&hb;
        ol.x = *(uint32_t*)&la; ol.y = *(uint32_t*)&lb;
        *(uint2*)(sWh + row * SHP + c4 * 4) = oh;
        *(uint2*)(sWl + row * SHP + c4 * 4) = ol;
    }
    if (tid < 128) sC[tid] = 0.f;
    __syncthreads();

    const int mt = wid & 1, koct = wid >> 1;
    const int rowB = (lane & 7) + ((lane >> 4) << 3);
    const int kB   = (lane & 8) ? 8 : 0;
    const int rowA = lane & 15;
    const int kA   = (lane >> 4) << 3;
    const uint32_t sWhu = smem_u32(sWh), sWlu = smem_u32(sWl);
    const uint32_t sHhu = smem_u32(sHh);

    uint32_t bH[4][2][2], bL[4][2][2];
#pragma unroll
    for (int kt = 0; kt < 4; kt++) {
        int kk = (koct * 4 + kt) * 16;
        uint32_t r4[4];
        LDMX4(r4, sWhu + (uint32_t)(rowB * SHP + kk + kB) * 2);
        bH[kt][0][0] = r4[0]; bH[kt][0][1] = r4[1];
        bH[kt][1][0] = r4[2]; bH[kt][1][1] = r4[3];
        LDMX4(r4, sWlu + (uint32_t)(rowB * SHP + kk + kB) * 2);
        bL[kt][0][0] = r4[0]; bL[kt][0][1] = r4[1];
        bL[kt][1][0] = r4[2]; bL[kt][1][1] = r4[3];
    }

    const int bb = tid >> 2, jl = tid & 3;
    const int jcol = j0 + jl;

    // step 0: h = 0
    if (tid < 128) {
        size_t gxb = (size_t)bb * GD + jcol;
        float gi = g_gx[gxb +    0];
        float gg = g_gx[gxb + 1024];
        float go = g_gx[gxb + 1536];
        float si = 1.f / (1.f + expf(-gi));
        float tg = tanhf(gg);
        float so = 1.f / (1.f + expf(-go));
        float c = si * tg;
        sC[tid] = c;
        float h = so * tanhf(c);
        __half hh = __float2half_rn(h);
        g_hs[(size_t)bb * 512 + jcol] = h;
        g_hsh[(size_t)bb * 512 + jcol] = hh;
        g_hbh[0][bb * 512 + jcol] = hh;
    }

    float4 pgx = make_float4(0.f, 0.f, 0.f, 0.f);
    if (tid < 128) {
        size_t gxb = ((size_t)32 + bb) * GD + jcol;
        pgx.x = __ldg(&g_gx[gxb +    0]);
        pgx.y = __ldg(&g_gx[gxb +  512]);
        pgx.z = __ldg(&g_gx[gxb + 1024]);
        pgx.w = __ldg(&g_gx[gxb + 1536]);
    }

    for (int t = 1; t < T1; t++) {
        grid_barrier_rel((unsigned)NCTA * (unsigned)t);

        {
            const __half* srcH = g_hbh[(t - 1) & 1];
#pragma unroll
            for (int it = 0; it < 4; it++) {
                int u = tid + it * 512;
                int row = u >> 6, c16 = u & 63;
                uint4 v = __ldcg((const uint4*)(srcH + row * 512 + c16 * 8));
                *(uint4*)(sHh + row * SHP + c16 * 8) = v;
            }
        }
        __syncthreads();

        float c0[4] = {0.f, 0.f, 0.f, 0.f};
        float c1[4] = {0.f, 0.f, 0.f, 0.f};
#pragma unroll
        for (int kt = 0; kt < 4; kt++) {
            int kk = (koct * 4 + kt) * 16;
            uint32_t aH[4];
            LDMX4(aH, sHhu + (uint32_t)((mt * 16 + rowA) * SHP + kk + kA) * 2);
            MMA16816F(c0, aH, bH[kt][0][0], bH[kt][0][1]);
            MMA16816F(c0, aH, bL[kt][0][0], bL[kt][0][1]);
            MMA16816F(c1, aH, bH[kt][1][0], bH[kt][1][1]);
            MMA16816F(c1, aH, bL[kt][1][0], bL[kt][1][1]);
        }
        {
            int r = lane >> 2, cc = (lane & 3) * 2;
            int b0 = mt * 16 + r, b1 = b0 + 8;
            float* p0 = sRed + (koct * 32 + b0) * SREDP;
            float* p1 = sRed + (koct * 32 + b1) * SREDP;
            *(float2*)(p0 + cc)     = make_float2(c0[0], c0[1]);
            *(float2*)(p1 + cc)     = make_float2(c0[2], c0[3]);
            *(float2*)(p0 + 8 + cc) = make_float2(c1[0], c1[1]);
            *(float2*)(p1 + 8 + cc) = make_float2(c1[2], c1[3]);
        }
        __syncthreads();

        if (tid < 128) {
            float s0 = 0.f, s1 = 0.f, s2 = 0.f, s3 = 0.f;
#pragma unroll
            for (int ko = 0; ko < 8; ko++) {
                const float* p = sRed + (ko * 32 + bb) * SREDP + jl;
                s0 += p[0]; s1 += p[4]; s2 += p[8]; s3 += p[12];
            }
            float gi = s0 + pgx.x;
            float gf = s1 + pgx.y;
            float gg = s2 + pgx.z;
            float go = s3 + pgx.w;
            float si = 1.f / (1.f + expf(-gi));
            float sf = 1.f / (1.f + expf(-gf));
            float tg = tanhf(gg);
            float so = 1.f / (1.f + expf(-go));
            float c = sf * sC[tid] + si * tg;
            sC[tid] = c;
            float h = so * tanhf(c);
            __half hh = __float2half_rn(h);
            g_hs[((size_t)t * 32 + bb) * 512 + jcol] = h;
            g_hsh[((size_t)t * 32 + bb) * 512 + jcol] = hh;
            g_hbh[t & 1][bb * 512 + jcol] = hh;
        }

        if (t + 1 < T1 && tid < 128) {
            size_t gxb = ((size_t)(t + 1) * 32 + bb) * GD + jcol;
            pgx.x = __ldg(&g_gx[gxb +    0]);
            pgx.y = __ldg(&g_gx[gxb +  512]);
            pgx.z = __ldg(&g_gx[gxb + 1024]);
            pgx.w = __ldg(&g_gx[gxb + 1536]);
        }
    }
}

// ---------------------------------------------------------------------------
// Logits GEMM: fp16 mma.sync, CTA 128x128, 512 threads, 16 warps (4m x 4n),
// warp tile 32x32 -> 16 resident warps/SM (2x R11). Per-tile row max kept.
// ---------------------------------------------------------------------------
#define ISSUE_CHUNK(ch) do { \
    int _buf = (ch) & 1; int _k0 = (ch) * 32; \
    int _r = tid >> 2, _c8 = (tid & 3) * 8; \
    int _gm = m0 + _r; \
    const __half* _srcA = g_hsh + (size_t)(_gm < MR ? _gm : 0) * HH + _k0 + _c8; \
    uint32_t _dstA = sAu + _buf * LBUFB + (_r * SAP + _c8) * 2; \
    int _szA = (_gm < MR) ? 16 : 0; \
    asm volatile("cp.async.cg.shared.global [%0], [%1], 16, %2;\n" \
                 :: "r"(_dstA), "l"(_srcA), "r"(_szA)); \
    const __half* _srcB = g_wh + (size_t)(n0 + _r) * HH + _k0 + _c8; \
    uint32_t _dstB = sBu + _buf * LBUFB + (_r * SAP + _c8) * 2; \
    asm volatile("cp.async.cg.shared.global [%0], [%1], 16;\n" \
                 :: "r"(_dstB), "l"(_srcB)); \
    asm volatile("cp.async.commit_group;\n"); \
} while (0)

__global__ __launch_bounds__(512) void gemm_logits_f16(
    const float* __restrict__ bias, float* __restrict__ out)
{
    __shared__ __half sA[2][128 * SAP];
    __shared__ __half sB[2][128 * SAP];
    __shared__ float sbias[128];
    __shared__ unsigned srmax[128];

    const int tid = threadIdx.x, lane = tid & 31, wid = tid >> 5;
    const int m0 = blockIdx.x * 128, n0 = blockIdx.y * 128;
    const int wm = (wid & 3) * 32, wn = (wid >> 2) * 32;
    const uint32_t LBUFB = 128 * SAP * 2;

    if (tid < 128) { sbias[tid] = bias[n0 + tid]; srmax[tid] = 0u; }

    const uint32_t sAu = smem_u32(sA);
    const uint32_t sBu = smem_u32(sB);

    const int rowA = lane & 15;
    const int kA   = (lane >> 4) << 3;
    const int rowB = (lane & 7) + ((lane >> 4) << 3);
    const int kB   = (lane & 8) ? 8 : 0;

    float c[2][4][4];
#pragma unroll
    for (int mi = 0; mi < 2; mi++)
#pragma unroll
        for (int ni = 0; ni < 4; ni++)
#pragma unroll
            for (int q = 0; q < 4; q++) c[mi][ni][q] = 0.f;

    ISSUE_CHUNK(0);

    for (int ch = 0; ch < 16; ch++) {
        const int buf = ch & 1;
        if (ch < 15) {
            ISSUE_CHUNK(ch + 1);
            asm volatile("cp.async.wait_group 1;\n");
        } else {
            asm volatile("cp.async.wait_group 0;\n");
        }
        __syncthreads();

#pragma unroll
        for (int kk = 0; kk < 32; kk += 16) {
            uint32_t aF[2][4], bF[4][2];
#pragma unroll
            for (int mi = 0; mi < 2; mi++) {
                uint32_t ad = sAu + buf * LBUFB +
                    (uint32_t)((wm + mi * 16 + rowA) * SAP + kk + kA) * 2;
                LDMX4(aF[mi], ad);
            }
#pragma unroll
            for (int nb = 0; nb < 2; nb++) {
                uint32_t r4[4];
                uint32_t bd = sBu + buf * LBUFB +
                    (uint32_t)((wn + nb * 16 + rowB) * SAP + kk + kB) * 2;
                LDMX4(r4, bd);
                bF[2 * nb][0] = r4[0]; bF[2 * nb][1] = r4[1];
                bF[2 * nb + 1][0] = r4[2]; bF[2 * nb + 1][1] = r4[3];
            }
#pragma unroll
            for (int mi = 0; mi < 2; mi++)
#pragma unroll
                for (int ni = 0; ni < 4; ni++)
                    MMA16816F(c[mi][ni], aF[mi], bF[ni][0], bF[ni][1]);
        }
        __syncthreads();
    }

    const int erow = lane >> 2;
    const int ecol = (lane & 3) * 2;
#pragma unroll
    for (int mi = 0; mi < 2; mi++) {
#pragma unroll
        for (int half = 0; half < 2; half++) {
            int mrow = wm + mi * 16 + erow + half * 8;
            int gm = m0 + mrow;
            if (gm < MR) {
                int tt = gm >> 5, b = gm & 31;
                float* dst = out + (size_t)(b * 63 + tt) * VV + n0 + wn;
                float mx = -INFINITY;
#pragma unroll
                for (int ni = 0; ni < 4; ni++) {
                    float2 o;
                    o.x = c[mi][ni][half * 2 + 0] + sbias[wn + ni * 8 + ecol + 0];
                    o.y = c[mi][ni][half * 2 + 1] + sbias[wn + ni * 8 + ecol + 1];
                    *(float2*)(dst + ni * 8 + ecol) = o;
                    mx = fmaxf(mx, fmaxf(o.x, o.y));
                }
                atomicMax(&srmax[mrow], fkey(mx));
            }
        }
    }
    __syncthreads();
    if (tid < 128) {
        int gm = m0 + tid;
        if (gm < MR) {
            int tt = gm >> 5, b = gm & 31;
            g_tmax[(size_t)(b * 63 + tt) * NTB + blockIdx.y] = srmax[tid];
        }
    }
}

// ---------------------------------------------------------------------------
// Rescue with block-skip (R11-proven, unchanged).
// ---------------------------------------------------------------------------
#define DELTA 0.01f
__global__ void rowmax_rescue(const float* __restrict__ logits,
                              const float* __restrict__ Wout,
                              const float* __restrict__ bout,
                              float* __restrict__ probs, float* __restrict__ pred)
{
    const int r = blockIdx.x;
    const int tid = threadIdx.x, lane = tid & 31, wid = tid >> 5;
    const float* row = logits + (size_t)r * VV;

    __shared__ unsigned skey[256];
    unsigned mk = 0u;
    for (int v = tid; v < NTB; v += 256) mk = max(mk, g_tmax[(size_t)r * NTB + v]);
    skey[tid] = mk;
    __syncthreads();
    for (int s = 128; s > 0; s >>= 1) {
        if (tid < s) skey[tid] = max(skey[tid], skey[tid + s]);
        __syncthreads();
    }
    const float amax = keyf(skey[0]);
    const float thresh = amax - DELTA;
    const unsigned tkey = fkey(thresh);
    __syncthreads();

    __shared__ int qblk[128];
    __shared__ int nq;
    if (tid == 0) nq = 0;
    __syncthreads();
    for (int v = tid; v < NTB; v += 256) {
        if (g_tmax[(size_t)r * NTB + v] > tkey) {
            int p = atomicAdd(&nq, 1);
            if (p < 128) qblk[p] = v;
        }
    }
    __syncthreads();
    const int nqq = min(nq, 128);

    __shared__ int cnt;
    __shared__ int cidx[128];
    __shared__ float cval[128];
    if (tid == 0) cnt = 0;
    __syncthreads();
    for (int q = 0; q < nqq; q++) {
        if (tid < 128) {
            int v = qblk[q] * 128 + tid;
            if (v < VV && row[v] > thresh) {
                int p = atomicAdd(&cnt, 1);
                if (p < 128) cidx[p] = v;
            }
        }
    }
    __syncthreads();
    const int n = min(cnt, 128);

    const int b = r / 63, t = r % 63;
    const float* h = g_hs + ((size_t)t * 32 + b) * HH;

    for (int ci = wid; ci < n; ci += 8) {
        const float* w = Wout + (size_t)cidx[ci] * HH;
        float s = 0.f;
        const int kb = lane * 16;
#pragma unroll
        for (int j = 0; j < 4; j++) {
            float4 hv = *(const float4*)(h + kb + j * 4);
            float4 wv = __ldg((const float4*)(w + kb + j * 4));
            s += hv.x * wv.x + hv.y * wv.y + hv.z * wv.z + hv.w * wv.w;
        }
#pragma unroll
        for (int off = 16; off > 0; off >>= 1)
            s += __shfl_xor_sync(0xFFFFFFFF, s, off);
        if (lane == 0) cval[ci] = s + __ldg(bout + cidx[ci]);
    }
    __syncthreads();

    if (tid == 0) {
        float bv = -INFINITY; int bi = VV;
        for (int i = 0; i < n; i++) {
            float v = cval[i]; int ix = cidx[i];
            if (v > bv || (v == bv && ix < bi)) { bv = v; bi = ix; }
        }
        probs[r] = bv;
        pred[r] = (float)bi;
    }
}

// ---------------------------------------------------------------------------
extern "C" void kernel_launch(void* const* d_in, const int* in_sizes, int n_in,
                              void* d_out, int out_size)
{
    const float* enc  = (const float*)d_in[0];
    const int*   cap  = (const int*)  d_in[1];
    const float* emb  = (const float*)d_in[2];
    const float* Wih  = (const float*)d_in[3];
    const float* Whh  = (const float*)d_in[4];
    const float* bih  = (const float*)d_in[5];
    const float* bhh  = (const float*)d_in[6];
    const float* Wout = (const float*)d_in[7];
    const float* bout = (const float*)d_in[8];
    float* out = (float*)d_out;

    cudaFuncSetAttribute(lstm_persist,
                         cudaFuncAttributeMaxDynamicSharedMemorySize, LSTM_SMEM_BYTES);
    cudaFuncSetAttribute(gemm_gx_f16,
                         cudaFuncAttributeMaxDynamicSharedMemorySize, GX_SMEM);

    convert_all<<<20064, 256>>>(Wout, Wih, enc, cap, emb);
    gemm_gx_f16<<<dim3(16, 16), 256, GX_SMEM>>>(bih, bhh);
    lstm_persist<<<NCTA, 512, LSTM_SMEM_BYTES>>>(Whh);
    gemm_logits_f16<<<dim3(16, NTB), 512>>>(bout, out);

    const long logits_elems = (long)BB * T1 * VV;
    if ((long)out_size >= logits_elems + 2L * BB * T1) {
        rowmax_rescue<<<MR, 256>>>(out, Wout, bout,
                                   out + logits_elems,
                                   out + logits_elems + (long)BB * T1);
    }
}

// round 14
// speedup vs baseline: 1.0298x; 1.0298x over previous
#include <cuda_runtime.h>
#include <cuda_bf16.h>
#include <cuda_fp16.h>
#include <math.h>
#include <stdint.h>

// Problem dims
#define T1 63
#define BB 32
#define HH 512
#define VV 32000
#define MR (T1*BB)       // 2016
#define GD (4*HH)        // 2048
#define NTB 250          // logits n-blocks (128 wide)

// Scratch (device globals)
__device__ float g_gx[(size_t)MR * GD];
__device__ float g_hs[(size_t)MR * HH];
__device__ float g_E[(size_t)BB * GD];        // enc@Wih[:, :512]^T + biases (fp32 exact)
__device__ unsigned g_bar;
__device__ __half g_wh[(size_t)VV * HH];      // W_out fp16
__device__ __half g_hsh[(size_t)MR * HH];     // h states fp16
__device__ __half g_wih_h[(size_t)GD * 512];  // W_ih[:,512:] hi
__device__ __half g_wih_l[(size_t)GD * 512];  // W_ih[:,512:] lo
__device__ __half g_xs_h[(size_t)MR * 512];   // emb_tok hi
__device__ __half g_xs_l[(size_t)MR * 512];   // emb_tok lo
__device__ __half g_hbh[2][BB * HH];          // h double-buffer (fp16)
__device__ unsigned g_tmax[(size_t)MR * NTB]; // per-(row, nblock) max key

#define NCTA 128
#define SHP 520
#define SREDP 18
#define LSTM_SMEM_BYTES ((32+16+16)*SHP*2 + 8*32*SREDP*4 + 128*4)  // 85,504

__device__ __forceinline__ uint32_t smem_u32(const void* p) {
    uint32_t a;
    asm("{ .reg .u64 t; cvta.to.shared.u64 t, %1; cvt.u32.u64 %0, t; }"
        : "=r"(a) : "l"(p));
    return a;
}
__device__ __forceinline__ unsigned fkey(float x) {
    unsigned u = __float_as_uint(x);
    return (u & 0x80000000u) ? ~u : (u | 0x80000000u);
}
__device__ __forceinline__ float keyf(unsigned k) {
    unsigned u = (k & 0x80000000u) ? (k & 0x7FFFFFFFu) : ~k;
    return __uint_as_float(u);
}

#define LDMX4(R, addr) \
    asm volatile("ldmatrix.sync.aligned.m8n8.x4.shared.b16 {%0,%1,%2,%3}, [%4];" \
        : "=r"((R)[0]), "=r"((R)[1]), "=r"((R)[2]), "=r"((R)[3]) : "r"(addr))

#define MMA16816F(C, A, B0, B1) \
    asm volatile("mma.sync.aligned.m16n8k16.row.col.f32.f16.f16.f32 " \
        "{%0,%1,%2,%3}, {%4,%5,%6,%7}, {%8,%9}, {%0,%1,%2,%3};" \
        : "+f"((C)[0]), "+f"((C)[1]), "+f"((C)[2]), "+f"((C)[3]) \
        : "r"((A)[0]), "r"((A)[1]), "r"((A)[2]), "r"((A)[3]), "r"(B0), "r"(B1))

__device__ __forceinline__ void split16(float x, __half& h, __half& l) {
    h = __float2half_rn(x);
    l = __float2half_rn(x - __half2float(h));
}

// ---------------------------------------------------------------------------
// Fat converter kernel.
//  [0,16000)      : W_out -> fp16
//  [16000,17024)  : W_ih[:,512:] -> hi/lo fp16 (emb K-half only)
//  [17024,18032)  : emb_tok gather -> hi/lo fp16
//  [18032,20080)  : E[b][n] = enc[b] . Wih[n][:512] + bih[n] + bhh[n] (fp32)
// ---------------------------------------------------------------------------
__global__ void convert_all(const float* __restrict__ Wout,
                            const float* __restrict__ Wih,
                            const float* __restrict__ enc,
                            const int* __restrict__ cap,
                            const float* __restrict__ emb,
                            const float* __restrict__ bih,
                            const float* __restrict__ bhh)
{
    const int bid = blockIdx.x;
    const int tid = threadIdx.x;
    if (bid == 0 && tid == 0) g_bar = 0u;

    if (bid < 16000) {
        size_t i = ((size_t)bid * 256 + tid) * 4;
        float4 v = *(const float4*)(Wout + i);
        __half2 a = __floats2half2_rn(v.x, v.y);
        __half2 b = __floats2half2_rn(v.z, v.w);
        uint2 o; o.x = *(uint32_t*)&a; o.y = *(uint32_t*)&b;
        *(uint2*)(g_wh + i) = o;
    } else if (bid < 17024) {
        int i4 = (bid - 16000) * 256 + tid;    // float4 index over [2048][512]
        int n = i4 >> 7, k = (i4 & 127) * 4;
        float4 v = *(const float4*)(Wih + (size_t)n * 1024 + 512 + k);
        __half h0, l0, h1, l1, h2, l2, h3, l3;
        split16(v.x, h0, l0); split16(v.y, h1, l1);
        split16(v.z, h2, l2); split16(v.w, h3, l3);
        __half2 ha = __halves2half2(h0, h1), hb = __halves2half2(h2, h3);
        __half2 la = __halves2half2(l0, l1), lb = __halves2half2(l2, l3);
        uint2 oh, ol;
        oh.x = *(uint32_t*)&ha; oh.y = *(uint32_t*)&hb;
        ol.x = *(uint32_t*)&la; ol.y = *(uint32_t*)&lb;
        size_t off = (size_t)n * 512 + k;
        *(uint2*)(g_wih_h + off) = oh;
        *(uint2*)(g_wih_l + off) = ol;
    } else if (bid < 18032) {
        int i4 = (bid - 17024) * 256 + tid;    // float4 index over [2016][512]
        int m = i4 >> 7, k = (i4 & 127) * 4;
        int tt = m >> 5, b = m & 31;
        const float* src = emb + (size_t)__ldg(cap + b * 64 + tt) * 512 + k;
        float4 v = *(const float4*)src;
        __half h0, l0, h1, l1, h2, l2, h3, l3;
        split16(v.x, h0, l0); split16(v.y, h1, l1);
        split16(v.z, h2, l2); split16(v.w, h3, l3);
        __half2 ha = __halves2half2(h0, h1), hb = __halves2half2(h2, h3);
        __half2 la = __halves2half2(l0, l1), lb = __halves2half2(l2, l3);
        uint2 oh, ol;
        oh.x = *(uint32_t*)&ha; oh.y = *(uint32_t*)&hb;
        ol.x = *(uint32_t*)&la; ol.y = *(uint32_t*)&lb;
        size_t off = (size_t)m * 512 + k;
        *(uint2*)(g_xs_h + off) = oh;
        *(uint2*)(g_xs_l + off) = ol;
    } else {
        // E: one block per n; 8 warps, each warp does b = w, w+8, w+16, w+24.
        const int n = bid - 18032;
        const int w = tid >> 5, lane = tid & 31;
        const float* wr = Wih + (size_t)n * 1024;   // cols [0,512)
        const float bsum = __ldg(bih + n) + __ldg(bhh + n);
#pragma unroll
        for (int ib = 0; ib < 4; ib++) {
            int b = w + ib * 8;
            const float* e = enc + b * 512;
            float s = 0.f;
#pragma unroll
            for (int j = 0; j < 4; j++) {
                float4 ev = *(const float4*)(e + lane * 16 + j * 4);
                float4 wv = __ldg((const float4*)(wr + lane * 16 + j * 4));
                s += ev.x * wv.x + ev.y * wv.y + ev.z * wv.z + ev.w * wv.w;
            }
#pragma unroll
            for (int off = 16; off > 0; off >>= 1)
                s += __shfl_xor_sync(0xFFFFFFFF, s, off);
            if (lane == 0) g_E[(size_t)b * GD + n] = s + bsum;
        }
    }
}

// ---------------------------------------------------------------------------
// gx GEMM (emb part only, K=512) via fp16x2-split mma.sync (3 passes).
// gx[m][n] = M + E[b][n].  CTA 128x128, k-chunk 32, 16 chunks.
// ---------------------------------------------------------------------------
#define SAP 40
#define TILEB (128 * SAP * 2)
#define BUFB  (2 * TILEB)
#define AB_REGION (2 * BUFB)
#define GX_SMEM (2 * AB_REGION + 512)

#define GX_ISSUE(ch) do { \
    int _buf = (ch) & 1; int _k0 = (ch) * 32; \
    _Pragma("unroll") \
    for (int _it = 0; _it < 8; _it++) { \
        const int _sel = _it >> 1; \
        int _rem = tid + (_it & 1) * 256; \
        int _r = _rem >> 2, _c8 = (_rem & 3) * 8; \
        uint32_t _dst = (_sel < 2 ? sAu : sBu) + _buf * BUFB \
                      + (_sel & 1) * TILEB + (uint32_t)(_r * SAP + _c8) * 2; \
        if (_sel < 2) { \
            int _gm = m0 + _r; \
            const __half* _src = (_sel == 0 ? g_xs_h : g_xs_l) \
                + (size_t)(_gm < MR ? _gm : 0) * 512 + _k0 + _c8; \
            int _sz = (_gm < MR) ? 16 : 0; \
            asm volatile("cp.async.cg.shared.global [%0], [%1], 16, %2;\n" \
                         :: "r"(_dst), "l"(_src), "r"(_sz)); \
        } else { \
            const __half* _src = (_sel == 2 ? g_wih_h : g_wih_l) \
                + (size_t)(n0 + _r) * 512 + _k0 + _c8; \
            asm volatile("cp.async.cg.shared.global [%0], [%1], 16;\n" \
                         :: "r"(_dst), "l"(_src)); \
        } \
    } \
    asm volatile("cp.async.commit_group;\n"); \
} while (0)

__global__ __launch_bounds__(256) void gemm_gx_f16()
{
    extern __shared__ char dyn[];
    const uint32_t sAu = smem_u32(dyn);
    const uint32_t sBu = sAu + AB_REGION;

    const int tid = threadIdx.x, lane = tid & 31, wid = tid >> 5;
    const int m0 = blockIdx.x * 128, n0 = blockIdx.y * 128;
    const int wm = (wid & 1) * 64, wn = (wid >> 1) * 32;

    const int rowA = lane & 15;
    const int kA   = (lane >> 4) << 3;
    const int rowB = (lane & 7) + ((lane >> 4) << 3);
    const int kB   = (lane & 8) ? 8 : 0;

    float c[4][4][4];
#pragma unroll
    for (int mi = 0; mi < 4; mi++)
#pragma unroll
        for (int ni = 0; ni < 4; ni++)
#pragma unroll
            for (int q = 0; q < 4; q++) c[mi][ni][q] = 0.f;

    GX_ISSUE(0);

    for (int ch = 0; ch < 16; ch++) {
        const int buf = ch & 1;
        if (ch < 15) {
            GX_ISSUE(ch + 1);
            asm volatile("cp.async.wait_group 1;\n");
        } else {
            asm volatile("cp.async.wait_group 0;\n");
        }
        __syncthreads();

#pragma unroll
        for (int kk = 0; kk < 32; kk += 16) {
            uint32_t aH[4][4], aL[4][4], bH[4][2], bL[4][2];
#pragma unroll
            for (int mi = 0; mi < 4; mi++) {
                uint32_t base = sAu + buf * BUFB +
                    (uint32_t)((wm + mi * 16 + rowA) * SAP + kk + kA) * 2;
                LDMX4(aH[mi], base);
                LDMX4(aL[mi], base + TILEB);
            }
#pragma unroll
            for (int nb = 0; nb < 2; nb++) {
                uint32_t base = sBu + buf * BUFB +
                    (uint32_t)((wn + nb * 16 + rowB) * SAP + kk + kB) * 2;
                uint32_t r4[4];
                LDMX4(r4, base);
                bH[2 * nb][0] = r4[0]; bH[2 * nb][1] = r4[1];
                bH[2 * nb + 1][0] = r4[2]; bH[2 * nb + 1][1] = r4[3];
                LDMX4(r4, base + TILEB);
                bL[2 * nb][0] = r4[0]; bL[2 * nb][1] = r4[1];
                bL[2 * nb + 1][0] = r4[2]; bL[2 * nb + 1][1] = r4[3];
            }
#pragma unroll
            for (int mi = 0; mi < 4; mi++)
#pragma unroll
                for (int ni = 0; ni < 4; ni++) {
                    MMA16816F(c[mi][ni], aH[mi], bH[ni][0], bH[ni][1]);
                    MMA16816F(c[mi][ni], aH[mi], bL[ni][0], bL[ni][1]);
                    MMA16816F(c[mi][ni], aL[mi], bH[ni][0], bH[ni][1]);
                }
        }
        __syncthreads();
    }

    const int erow = lane >> 2;
    const int ecol = (lane & 3) * 2;
#pragma unroll
    for (int mi = 0; mi < 4; mi++) {
#pragma unroll
        for (int half = 0; half < 2; half++) {
            int gm = m0 + wm + mi * 16 + erow + half * 8;
            if (gm < MR) {
                int b = gm & 31;
                float* dst = g_gx + (size_t)gm * GD + n0 + wn;
                const float* Eb = g_E + (size_t)b * GD + n0 + wn;
#pragma unroll
                for (int ni = 0; ni < 4; ni++) {
                    float2 ev = *(const float2*)(Eb + ni * 8 + ecol);
                    float2 o;
                    o.x = c[mi][ni][half * 2 + 0] + ev.x;
                    o.y = c[mi][ni][half * 2 + 1] + ev.y;
                    *(float2*)(dst + ni * 8 + ecol) = o;
                }
            }
        }
    }
}

// ---------------------------------------------------------------------------
// Persistent LSTM (R11-proven, unchanged).
// ---------------------------------------------------------------------------
__device__ __forceinline__ void grid_barrier_rel(unsigned target) {
    __syncthreads();
    if (threadIdx.x == 0) {
        unsigned a;
        asm volatile("atom.release.gpu.global.add.u32 %0, [%1], 1;"
                     : "=r"(a) : "l"(&g_bar) : "memory");
        a += 1;
        if (a < target) {
            unsigned v;
            do {
                asm volatile("ld.acquire.gpu.global.u32 %0, [%1];"
                             : "=r"(v) : "l"(&g_bar) : "memory");
            } while (v < target);
        }
    }
    __syncthreads();
}

__global__ __launch_bounds__(512, 1) void lstm_persist(const float* __restrict__ Whh)
{
    extern __shared__ char dsm[];
    __half* sHh = (__half*)dsm;                 // [32][SHP]
    __half* sWh = sHh + 32 * SHP;               // [16][SHP]
    __half* sWl = sWh + 16 * SHP;               // [16][SHP]
    float*  sRed = (float*)(sWl + 16 * SHP);    // [8][32][SREDP]
    float*  sC   = sRed + 8 * 32 * SREDP;       // [128]

    const int tid = threadIdx.x, lane = tid & 31, wid = tid >> 5;
    const int j0 = blockIdx.x * 4;

    for (int i = tid; i < 16 * 128; i += 512) {
        int row = i >> 7, c4 = i & 127;
        int g = row >> 2, j = row & 3;
        float4 v = *(const float4*)(Whh + (size_t)(g * 512 + j0 + j) * 512 + c4 * 4);
        __half h0, l0, h1, l1, h2, l2, h3, l3;
        split16(v.x, h0, l0); split16(v.y, h1, l1);
        split16(v.z, h2, l2); split16(v.w, h3, l3);
        __half2 ha = __halves2half2(h0, h1), hb = __halves2half2(h2, h3);
        __half2 la = __halves2half2(l0, l1), lb = __halves2half2(l2, l3);
        uint2 oh, ol;
        oh.x = *(uint32_t*)&ha; oh.y = *(uint32_t*)&hb;
        ol.x = *(uint32_t*)&la; ol.y = *(uint32_t*)&lb;
        *(uint2*)(sWh + row * SHP + c4 * 4) = oh;
        *(uint2*)(sWl + row * SHP + c4 * 4) = ol;
    }
    if (tid < 128) sC[tid] = 0.f;
    __syncthreads();

    const int mt = wid & 1, koct = wid >> 1;
    const int rowB = (lane & 7) + ((lane >> 4) << 3);
    const int kB   = (lane & 8) ? 8 : 0;
    const int rowA = lane & 15;
    const int kA   = (lane >> 4) << 3;
    const uint32_t sWhu = smem_u32(sWh), sWlu = smem_u32(sWl);
    const uint32_t sHhu = smem_u32(sHh);

    uint32_t bH[4][2][2], bL[4][2][2];
#pragma unroll
    for (int kt = 0; kt < 4; kt++) {
        int kk = (koct * 4 + kt) * 16;
        uint32_t r4[4];
        LDMX4(r4, sWhu + (uint32_t)(rowB * SHP + kk + kB) * 2);
        bH[kt][0][0] = r4[0]; bH[kt][0][1] = r4[1];
        bH[kt][1][0] = r4[2]; bH[kt][1][1] = r4[3];
        LDMX4(r4, sWlu + (uint32_t)(rowB * SHP + kk + kB) * 2);
        bL[kt][0][0] = r4[0]; bL[kt][0][1] = r4[1];
        bL[kt][1][0] = r4[2]; bL[kt][1][1] = r4[3];
    }

    const int bb = tid >> 2, jl = tid & 3;
    const int jcol = j0 + jl;

    if (tid < 128) {
        size_t gxb = (size_t)bb * GD + jcol;
        float gi = g_gx[gxb +    0];
        float gg = g_gx[gxb + 1024];
        float go = g_gx[gxb + 1536];
        float si = 1.f / (1.f + expf(-gi));
        float tg = tanhf(gg);
        float so = 1.f / (1.f + expf(-go));
        float c = si * tg;
        sC[tid] = c;
        float h = so * tanhf(c);
        __half hh = __float2half_rn(h);
        g_hs[(size_t)bb * 512 + jcol] = h;
        g_hsh[(size_t)bb * 512 + jcol] = hh;
        g_hbh[0][bb * 512 + jcol] = hh;
    }

    float4 pgx = make_float4(0.f, 0.f, 0.f, 0.f);
    if (tid < 128) {
        size_t gxb = ((size_t)32 + bb) * GD + jcol;
        pgx.x = __ldg(&g_gx[gxb +    0]);
        pgx.y = __ldg(&g_gx[gxb +  512]);
        pgx.z = __ldg(&g_gx[gxb + 1024]);
        pgx.w = __ldg(&g_gx[gxb + 1536]);
    }

    for (int t = 1; t < T1; t++) {
        grid_barrier_rel((unsigned)NCTA * (unsigned)t);

        {
            const __half* srcH = g_hbh[(t - 1) & 1];
#pragma unroll
            for (int it = 0; it < 4; it++) {
                int u = tid + it * 512;
                int row = u >> 6, c16 = u & 63;
                uint4 v = __ldcg((const uint4*)(srcH + row * 512 + c16 * 8));
                *(uint4*)(sHh + row * SHP + c16 * 8) = v;
            }
        }
        __syncthreads();

        float c0[4] = {0.f, 0.f, 0.f, 0.f};
        float c1[4] = {0.f, 0.f, 0.f, 0.f};
#pragma unroll
        for (int kt = 0; kt < 4; kt++) {
            int kk = (koct * 4 + kt) * 16;
            uint32_t aH[4];
            LDMX4(aH, sHhu + (uint32_t)((mt * 16 + rowA) * SHP + kk + kA) * 2);
            MMA16816F(c0, aH, bH[kt][0][0], bH[kt][0][1]);
            MMA16816F(c0, aH, bL[kt][0][0], bL[kt][0][1]);
            MMA16816F(c1, aH, bH[kt][1][0], bH[kt][1][1]);
            MMA16816F(c1, aH, bL[kt][1][0], bL[kt][1][1]);
        }
        {
            int r = lane >> 2, cc = (lane & 3) * 2;
            int b0 = mt * 16 + r, b1 = b0 + 8;
            float* p0 = sRed + (koct * 32 + b0) * SREDP;
            float* p1 = sRed + (koct * 32 + b1) * SREDP;
            *(float2*)(p0 + cc)     = make_float2(c0[0], c0[1]);
            *(float2*)(p1 + cc)     = make_float2(c0[2], c0[3]);
            *(float2*)(p0 + 8 + cc) = make_float2(c1[0], c1[1]);
            *(float2*)(p1 + 8 + cc) = make_float2(c1[2], c1[3]);
        }
        __syncthreads();

        if (tid < 128) {
            float s0 = 0.f, s1 = 0.f, s2 = 0.f, s3 = 0.f;
#pragma unroll
            for (int ko = 0; ko < 8; ko++) {
                const float* p = sRed + (ko * 32 + bb) * SREDP + jl;
                s0 += p[0]; s1 += p[4]; s2 += p[8]; s3 += p[12];
            }
            float gi = s0 + pgx.x;
            float gf = s1 + pgx.y;
            float gg = s2 + pgx.z;
            float go = s3 + pgx.w;
            float si = 1.f / (1.f + expf(-gi));
            float sf = 1.f / (1.f + expf(-gf));
            float tg = tanhf(gg);
            float so = 1.f / (1.f + expf(-go));
            float c = sf * sC[tid] + si * tg;
            sC[tid] = c;
            float h = so * tanhf(c);
            __half hh = __float2half_rn(h);
            g_hs[((size_t)t * 32 + bb) * 512 + jcol] = h;
            g_hsh[((size_t)t * 32 + bb) * 512 + jcol] = hh;
            g_hbh[t & 1][bb * 512 + jcol] = hh;
        }

        if (t + 1 < T1 && tid < 128) {
            size_t gxb = ((size_t)(t + 1) * 32 + bb) * GD + jcol;
            pgx.x = __ldg(&g_gx[gxb +    0]);
            pgx.y = __ldg(&g_gx[gxb +  512]);
            pgx.z = __ldg(&g_gx[gxb + 1024]);
            pgx.w = __ldg(&g_gx[gxb + 1536]);
        }
    }
}

// ---------------------------------------------------------------------------
// Logits GEMM: fp16 mma.sync, CTA 128x128, 512 threads (R12 config; at the
// legacy-HMMA throughput floor ~253us).
// ---------------------------------------------------------------------------
#define ISSUE_CHUNK(ch) do { \
    int _buf = (ch) & 1; int _k0 = (ch) * 32; \
    int _r = tid >> 2, _c8 = (tid & 3) * 8; \
    int _gm = m0 + _r; \
    const __half* _srcA = g_hsh + (size_t)(_gm < MR ? _gm : 0) * HH + _k0 + _c8; \
    uint32_t _dstA = sAu + _buf * LBUFB + (_r * SAP + _c8) * 2; \
    int _szA = (_gm < MR) ? 16 : 0; \
    asm volatile("cp.async.cg.shared.global [%0], [%1], 16, %2;\n" \
                 :: "r"(_dstA), "l"(_srcA), "r"(_szA)); \
    const __half* _srcB = g_wh + (size_t)(n0 + _r) * HH + _k0 + _c8; \
    uint32_t _dstB = sBu + _buf * LBUFB + (_r * SAP + _c8) * 2; \
    asm volatile("cp.async.cg.shared.global [%0], [%1], 16;\n" \
                 :: "r"(_dstB), "l"(_srcB)); \
    asm volatile("cp.async.commit_group;\n"); \
} while (0)

__global__ __launch_bounds__(512) void gemm_logits_f16(
    const float* __restrict__ bias, float* __restrict__ out)
{
    __shared__ __half sA[2][128 * SAP];
    __shared__ __half sB[2][128 * SAP];
    __shared__ float sbias[128];
    __shared__ unsigned srmax[128];

    const int tid = threadIdx.x, lane = tid & 31, wid = tid >> 5;
    const int m0 = blockIdx.x * 128, n0 = blockIdx.y * 128;
    const int wm = (wid & 3) * 32, wn = (wid >> 2) * 32;
    const uint32_t LBUFB = 128 * SAP * 2;

    if (tid < 128) { sbias[tid] = bias[n0 + tid]; srmax[tid] = 0u; }

    const uint32_t sAu = smem_u32(sA);
    const uint32_t sBu = smem_u32(sB);

    const int rowA = lane & 15;
    const int kA   = (lane >> 4) << 3;
    const int rowB = (lane & 7) + ((lane >> 4) << 3);
    const int kB   = (lane & 8) ? 8 : 0;

    float c[2][4][4];
#pragma unroll
    for (int mi = 0; mi < 2; mi++)
#pragma unroll
        for (int ni = 0; ni < 4; ni++)
#pragma unroll
            for (int q = 0; q < 4; q++) c[mi][ni][q] = 0.f;

    ISSUE_CHUNK(0);

    for (int ch = 0; ch < 16; ch++) {
        const int buf = ch & 1;
        if (ch < 15) {
            ISSUE_CHUNK(ch + 1);
            asm volatile("cp.async.wait_group 1;\n");
        } else {
            asm volatile("cp.async.wait_group 0;\n");
        }
        __syncthreads();

#pragma unroll
        for (int kk = 0; kk < 32; kk += 16) {
            uint32_t aF[2][4], bF[4][2];
#pragma unroll
            for (int mi = 0; mi < 2; mi++) {
                uint32_t ad = sAu + buf * LBUFB +
                    (uint32_t)((wm + mi * 16 + rowA) * SAP + kk + kA) * 2;
                LDMX4(aF[mi], ad);
            }
#pragma unroll
            for (int nb = 0; nb < 2; nb++) {
                uint32_t r4[4];
                uint32_t bd = sBu + buf * LBUFB +
                    (uint32_t)((wn + nb * 16 + rowB) * SAP + kk + kB) * 2;
                LDMX4(r4, bd);
                bF[2 * nb][0] = r4[0]; bF[2 * nb][1] = r4[1];
                bF[2 * nb + 1][0] = r4[2]; bF[2 * nb + 1][1] = r4[3];
            }
#pragma unroll
            for (int mi = 0; mi < 2; mi++)
#pragma unroll
                for (int ni = 0; ni < 4; ni++)
                    MMA16816F(c[mi][ni], aF[mi], bF[ni][0], bF[ni][1]);
        }
        __syncthreads();
    }

    const int erow = lane >> 2;
    const int ecol = (lane & 3) * 2;
#pragma unroll
    for (int mi = 0; mi < 2; mi++) {
#pragma unroll
        for (int half = 0; half < 2; half++) {
            int mrow = wm + mi * 16 + erow + half * 8;
            int gm = m0 + mrow;
            if (gm < MR) {
                int tt = gm >> 5, b = gm & 31;
                float* dst = out + (size_t)(b * 63 + tt) * VV + n0 + wn;
                float mx = -INFINITY;
#pragma unroll
                for (int ni = 0; ni < 4; ni++) {
                    float2 o;
                    o.x = c[mi][ni][half * 2 + 0] + sbias[wn + ni * 8 + ecol + 0];
                    o.y = c[mi][ni][half * 2 + 1] + sbias[wn + ni * 8 + ecol + 1];
                    *(float2*)(dst + ni * 8 + ecol) = o;
                    mx = fmaxf(mx, fmaxf(o.x, o.y));
                }
                atomicMax(&srmax[mrow], fkey(mx));
            }
        }
    }
    __syncthreads();
    if (tid < 128) {
        int gm = m0 + tid;
        if (gm < MR) {
            int tt = gm >> 5, b = gm & 31;
            g_tmax[(size_t)(b * 63 + tt) * NTB + blockIdx.y] = srmax[tid];
        }
    }
}

// ---------------------------------------------------------------------------
// Rescue with block-skip (R11-proven, unchanged).
// ---------------------------------------------------------------------------
#define DELTA 0.01f
__global__ void rowmax_rescue(const float* __restrict__ logits,
                              const float* __restrict__ Wout,
                              const float* __restrict__ bout,
                              float* __restrict__ probs, float* __restrict__ pred)
{
    const int r = blockIdx.x;
    const int tid = threadIdx.x, lane = tid & 31, wid = tid >> 5;
    const float* row = logits + (size_t)r * VV;

    __shared__ unsigned skey[256];
    unsigned mk = 0u;
    for (int v = tid; v < NTB; v += 256) mk = max(mk, g_tmax[(size_t)r * NTB + v]);
    skey[tid] = mk;
    __syncthreads();
    for (int s = 128; s > 0; s >>= 1) {
        if (tid < s) skey[tid] = max(skey[tid], skey[tid + s]);
        __syncthreads();
    }
    const float amax = keyf(skey[0]);
    const float thresh = amax - DELTA;
    const unsigned tkey = fkey(thresh);
    __syncthreads();

    __shared__ int qblk[128];
    __shared__ int nq;
    if (tid == 0) nq = 0;
    __syncthreads();
    for (int v = tid; v < NTB; v += 256) {
        if (g_tmax[(size_t)r * NTB + v] > tkey) {
            int p = atomicAdd(&nq, 1);
            if (p < 128) qblk[p] = v;
        }
    }
    __syncthreads();
    const int nqq = min(nq, 128);

    __shared__ int cnt;
    __shared__ int cidx[128];
    __shared__ float cval[128];
    if (tid == 0) cnt = 0;
    __syncthreads();
    for (int q = 0; q < nqq; q++) {
        if (tid < 128) {
            int v = qblk[q] * 128 + tid;
            if (v < VV && row[v] > thresh) {
                int p = atomicAdd(&cnt, 1);
                if (p < 128) cidx[p] = v;
            }
        }
    }
    __syncthreads();
    const int n = min(cnt, 128);

    const int b = r / 63, t = r % 63;
    const float* h = g_hs + ((size_t)t * 32 + b) * HH;

    for (int ci = wid; ci < n; ci += 8) {
        const float* w = Wout + (size_t)cidx[ci] * HH;
        float s = 0.f;
        const int kb = lane * 16;
#pragma unroll
        for (int j = 0; j < 4; j++) {
            float4 hv = *(const float4*)(h + kb + j * 4);
            float4 wv = __ldg((const float4*)(w + kb + j * 4));
            s += hv.x * wv.x + hv.y * wv.y + hv.z * wv.z + hv.w * wv.w;
        }
#pragma unroll
        for (int off = 16; off > 0; off >>= 1)
            s += __shfl_xor_sync(0xFFFFFFFF, s, off);
        if (lane == 0) cval[ci] = s + __ldg(bout + cidx[ci]);
    }
    __syncthreads();

    if (tid == 0) {
        float bv = -INFINITY; int bi = VV;
        for (int i = 0; i < n; i++) {
            float v = cval[i]; int ix = cidx[i];
            if (v > bv || (v == bv && ix < bi)) { bv = v; bi = ix; }
        }
        probs[r] = bv;
        pred[r] = (float)bi;
    }
}

// ---------------------------------------------------------------------------
extern "C" void kernel_launch(void* const* d_in, const int* in_sizes, int n_in,
                              void* d_out, int out_size)
{
    const float* enc  = (const float*)d_in[0];
    const int*   cap  = (const int*)  d_in[1];
    const float* emb  = (const float*)d_in[2];
    const float* Wih  = (const float*)d_in[3];
    const float* Whh  = (const float*)d_in[4];
    const float* bih  = (const float*)d_in[5];
    const float* bhh  = (const float*)d_in[6];
    const float* Wout = (const float*)d_in[7];
    const float* bout = (const float*)d_in[8];
    float* out = (float*)d_out;

    cudaFuncSetAttribute(lstm_persist,
                         cudaFuncAttributeMaxDynamicSharedMemorySize, LSTM_SMEM_BYTES);
    cudaFuncSetAttribute(gemm_gx_f16,
                         cudaFuncAttributeMaxDynamicSharedMemorySize, GX_SMEM);

    convert_all<<<20080, 256>>>(Wout, Wih, enc, cap, emb, bih, bhh);
    gemm_gx_f16<<<dim3(16, 16), 256, GX_SMEM>>>();
    lstm_persist<<<NCTA, 512, LSTM_SMEM_BYTES>>>(Whh);
    gemm_logits_f16<<<dim3(16, NTB), 512>>>(bout, out);

    const long logits_elems = (long)BB * T1 * VV;
    if ((long)out_size >= logits_elems + 2L * BB * T1) {
        rowmax_rescue<<<MR, 256>>>(out, Wout, bout,
                                   out + logits_elems,
                                   out + logits_elems + (long)BB * T1);
    }
}